// round 10
// baseline (speedup 1.0000x reference)
#include <cuda_runtime.h>
#include <cstdint>

#define LEAK   0.95f
#define THRESH 1.0f
#define LN_EPS 1e-5f

#define CHUNK 128     // output steps per scan chunk (validated best)
#define WARM  256     // warm-up steps before each chunk (validated boundary)
#define SPF   16      // steps per prefetch buffer

// Scratch for x in case d_out only holds spikes (fallback; normally x goes to
// the second half of d_out).
__device__ float g_xbuf[8u * 2048u * 768u];

// ---------------------------------------------------------------------------
// Kernel 1: x = LayerNorm(emb_w[token] + pos_w[s]) * gamma + beta
// One block per position s; warp w handles batch b=w (all warps share pos[s]).
// All 12 row loads (emb + pos) are batched before any arithmetic -> MLP=12.
// gamma/beta loads stay in the output loop (R7 showed hoisting them regresses).
// ---------------------------------------------------------------------------
__global__ void __launch_bounds__(256) emb_ln_kernel(
    const int* __restrict__ tok,
    const float* __restrict__ emb,
    const float* __restrict__ pos,
    const float* __restrict__ gamma,
    const float* __restrict__ beta,
    float* __restrict__ xout,
    int B, int S, int D)
{
    int s = blockIdx.x;
    int b = threadIdx.x >> 5;
    int lane = threadIdx.x & 31;
    if (b >= B) return;

    int row = b * S + s;
    int t = __ldg(tok + row);

    const int D4 = D >> 2;             // 192
    const int NV = D >> 7;             // 6

    const float4* e4 = reinterpret_cast<const float4*>(emb) + (size_t)t * D4;
    const float4* p4 = reinterpret_cast<const float4*>(pos) + (size_t)s * D4;

    // Batch all loads first: 12 outstanding LDG.128 per thread.
    float4 e[6], p[6];
#pragma unroll 6
    for (int k = 0; k < NV; k++) {
        e[k] = __ldcs(e4 + (lane + (k << 5)));   // streaming: keep L2 for x
    }
#pragma unroll 6
    for (int k = 0; k < NV; k++) {
        p[k] = __ldg(p4 + (lane + (k << 5)));
    }

    float4 v[6];
    float sum = 0.f, ss = 0.f;
#pragma unroll 6
    for (int k = 0; k < NV; k++) {
        float4 r;
        r.x = e[k].x + p[k].x; r.y = e[k].y + p[k].y;
        r.z = e[k].z + p[k].z; r.w = e[k].w + p[k].w;
        v[k] = r;
        sum += (r.x + r.y) + (r.z + r.w);
        ss = fmaf(r.x, r.x, ss);
        ss = fmaf(r.y, r.y, ss);
        ss = fmaf(r.z, r.z, ss);
        ss = fmaf(r.w, r.w, ss);
    }
#pragma unroll
    for (int o = 16; o > 0; o >>= 1) {
        sum += __shfl_xor_sync(0xffffffffu, sum, o);
        ss  += __shfl_xor_sync(0xffffffffu, ss,  o);
    }
    float inv_d = 1.0f / (float)D;
    float mu  = sum * inv_d;
    float var = fmaf(-mu, mu, ss * inv_d);
    float rstd = rsqrtf(var + LN_EPS);

    const float4* g4 = reinterpret_cast<const float4*>(gamma);
    const float4* b4 = reinterpret_cast<const float4*>(beta);
    float4* xo = reinterpret_cast<float4*>(xout) + (size_t)row * D4;

#pragma unroll 6
    for (int k = 0; k < NV; k++) {
        int idx = lane + (k << 5);
        float4 g = __ldg(g4 + idx);
        float4 bb = __ldg(b4 + idx);
        float4 r = v[k];
        float4 o;
        o.x = (r.x - mu) * rstd * g.x + bb.x;
        o.y = (r.y - mu) * rstd * g.y + bb.y;
        o.z = (r.z - mu) * rstd * g.z + bb.z;
        o.w = (r.w - mu) * rstd * g.w + bb.w;
        xo[idx] = o;                        // cache in L2 (re-read by scan)
    }
}

// ---------------------------------------------------------------------------
// Kernel 2: chunked LIF scan, 2 chains per thread (float2), FSET-based step,
// compile-time D2 so all strided addresses fold to [reg+imm].
//   vr = v*LEAK + x_t ; s = (vr >= 1) as 1.0/0.0 (FSET) ; v = vr - s*vr
// Bit-identical to compare/select: s=1 -> v=0, s=0 -> v=vr.
// Each chunk (blockIdx.y) re-derives state with up to WARM warm-up steps
// from v=0 (chunks starting at t0 <= WARM warm from t=0 and are exact;
// later chunks rely on 0.95^256 decay + exact reset resynchronization).
// ---------------------------------------------------------------------------
__device__ __forceinline__ float fset_ge_thr(float a) {
    float r;
    asm("set.ge.f32.f32 %0, %1, %2;" : "=f"(r) : "f"(a), "f"(THRESH));
    return r;
}

__device__ __forceinline__ float lif_step(float& v, float xin) {
    float vr = fmaf(v, LEAK, xin);      // FFMA-imm (rt=1)
    float s = fset_ge_thr(vr);          // FSET -> {0.0f, 1.0f}
    v = fmaf(-s, vr, vr);               // exact reset
    return s;
}

template<int D2C>
__global__ void __launch_bounds__(128) lif_scan2_c(
    const float2* __restrict__ x,
    float2* __restrict__ spk,
    int S, int B)
{
    int q = blockIdx.x * blockDim.x + (int)threadIdx.x;   // chain-pair id
    int b = q / D2C;
    int d = q - b * D2C;
    if (b >= B) return;

    int t0 = blockIdx.y * CHUNK;
    int n_w = (t0 < WARM) ? t0 : WARM;             // multiple of 2*SPF
    int tw = t0 - n_w;
    int total = n_w + CHUNK;

    const float2* xp = x   + ((size_t)b * S + tw) * D2C + d;
    float2*       sp = spk + ((size_t)b * S + t0) * D2C + d;

    float2 A[SPF], Bb[SPF];
#pragma unroll
    for (int i = 0; i < SPF; i++)
        A[i] = __ldg(xp + (size_t)i * D2C);

    float vx = 0.f, vy = 0.f;

    for (int s0 = 0; s0 < total; s0 += 2 * SPF) {
        // prefetch second half of this 32-step window
        {
            const float2* p = xp + (size_t)(s0 + SPF) * D2C;
#pragma unroll
            for (int i = 0; i < SPF; i++)
                Bb[i] = __ldg(p + (size_t)i * D2C);
        }
        // process A: steps [s0, s0+SPF)
        if (s0 >= n_w) {
            float2* o = sp + (size_t)(s0 - n_w) * D2C;
#pragma unroll
            for (int i = 0; i < SPF; i++) {
                float2 sv;
                sv.x = lif_step(vx, A[i].x);
                sv.y = lif_step(vy, A[i].y);
                __stcs(o + (size_t)i * D2C, sv);
            }
        } else {
#pragma unroll
            for (int i = 0; i < SPF; i++) {
                lif_step(vx, A[i].x);
                lif_step(vy, A[i].y);
            }
        }
        // prefetch first half of next window
        if (s0 + 2 * SPF < total) {
            const float2* p = xp + (size_t)(s0 + 2 * SPF) * D2C;
#pragma unroll
            for (int i = 0; i < SPF; i++)
                A[i] = __ldg(p + (size_t)i * D2C);
        }
        // process B: steps [s0+SPF, s0+2*SPF)
        int sB = s0 + SPF;
        if (sB >= n_w) {
            float2* o = sp + (size_t)(sB - n_w) * D2C;
#pragma unroll
            for (int i = 0; i < SPF; i++) {
                float2 sv;
                sv.x = lif_step(vx, Bb[i].x);
                sv.y = lif_step(vy, Bb[i].y);
                __stcs(o + (size_t)i * D2C, sv);
            }
        } else {
#pragma unroll
            for (int i = 0; i < SPF; i++) {
                lif_step(vx, Bb[i].x);
                lif_step(vy, Bb[i].y);
            }
        }
    }
}

// Generic fallback (runtime D2) — same algorithm.
__global__ void __launch_bounds__(128) lif_scan2_g(
    const float2* __restrict__ x,
    float2* __restrict__ spk,
    int S, int D2, int B)
{
    int q = blockIdx.x * blockDim.x + (int)threadIdx.x;
    int b = q / D2;
    int d = q - b * D2;
    if (b >= B) return;

    int t0 = blockIdx.y * CHUNK;
    int n_w = (t0 < WARM) ? t0 : WARM;
    int tw = t0 - n_w;
    int total = n_w + CHUNK;

    const float2* xp = x   + ((size_t)b * S + tw) * D2 + d;
    float2*       sp = spk + ((size_t)b * S + t0) * D2 + d;

    float2 A[SPF], Bb[SPF];
#pragma unroll
    for (int i = 0; i < SPF; i++)
        A[i] = __ldg(xp + (size_t)i * D2);

    float vx = 0.f, vy = 0.f;

    for (int s0 = 0; s0 < total; s0 += 2 * SPF) {
        {
            const float2* p = xp + (size_t)(s0 + SPF) * D2;
#pragma unroll
            for (int i = 0; i < SPF; i++)
                Bb[i] = __ldg(p + (size_t)i * D2);
        }
        if (s0 >= n_w) {
            float2* o = sp + (size_t)(s0 - n_w) * D2;
#pragma unroll
            for (int i = 0; i < SPF; i++) {
                float2 sv;
                sv.x = lif_step(vx, A[i].x);
                sv.y = lif_step(vy, A[i].y);
                __stcs(o + (size_t)i * D2, sv);
            }
        } else {
#pragma unroll
            for (int i = 0; i < SPF; i++) {
                lif_step(vx, A[i].x);
                lif_step(vy, A[i].y);
            }
        }
        if (s0 + 2 * SPF < total) {
            const float2* p = xp + (size_t)(s0 + 2 * SPF) * D2;
#pragma unroll
            for (int i = 0; i < SPF; i++)
                A[i] = __ldg(p + (size_t)i * D2);
        }
        int sB = s0 + SPF;
        if (sB >= n_w) {
            float2* o = sp + (size_t)(sB - n_w) * D2;
#pragma unroll
            for (int i = 0; i < SPF; i++) {
                float2 sv;
                sv.x = lif_step(vx, Bb[i].x);
                sv.y = lif_step(vy, Bb[i].y);
                __stcs(o + (size_t)i * D2, sv);
            }
        } else {
#pragma unroll
            for (int i = 0; i < SPF; i++) {
                lif_step(vx, Bb[i].x);
                lif_step(vy, Bb[i].y);
            }
        }
    }
}

// ---------------------------------------------------------------------------
// Launch. Inputs (metadata order): token_ids [B,S] i32, emb_w [V,D] f32,
// pos_w [S,D] f32, gamma [D] f32, beta [D] f32.
// Output: (spikes [B,S,D], x [B,S,D]) concatenated.
// ---------------------------------------------------------------------------
extern "C" void kernel_launch(void* const* d_in, const int* in_sizes, int n_in,
                              void* d_out, int out_size)
{
    const int*   tok   = (const int*)d_in[0];
    const float* emb   = (const float*)d_in[1];
    const float* pos   = (const float*)d_in[2];
    const float* gamma = (const float*)d_in[3];
    const float* beta  = (const float*)d_in[4];

    int BS = in_sizes[0];          // B*S
    int D  = in_sizes[3];          // 768
    int SD = in_sizes[2];          // S*D
    int S  = SD / D;
    int B  = BS / S;

    size_t BSD = (size_t)BS * (size_t)D;

    float* spikes = (float*)d_out;
    float* xout;
    if ((size_t)out_size >= 2 * BSD) {
        xout = spikes + BSD;       // x is second half of the tuple output
    } else {
        cudaGetSymbolAddress((void**)&xout, g_xbuf);
    }

    // Kernel 1: one block per position s, warp per batch b.
    emb_ln_kernel<<<S, 32 * B>>>(tok, emb, pos, gamma, beta, xout, B, S, D);

    // Kernel 2: 2 chains per thread, 128-thread blocks, chunks along y.
    int D2 = D >> 1;                         // 384
    int ngrp = B * D2;                       // 3072
    dim3 grid2((ngrp + 127) / 128, (S + CHUNK - 1) / CHUNK);
    if (D2 == 384) {
        lif_scan2_c<384><<<grid2, 128>>>((const float2*)xout, (float2*)spikes, S, B);
    } else {
        lif_scan2_g<<<grid2, 128>>>((const float2*)xout, (float2*)spikes, S, D2, B);
    }
}

// round 12
// speedup vs baseline: 1.4472x; 1.4472x over previous
#include <cuda_runtime.h>
#include <cstdint>

#define LEAK   0.95f
#define THRESH 1.0f
#define LN_EPS 1e-5f

#define CHUNK 128     // output steps per scan chunk (validated best)
#define WARM  256     // warm-up steps before each chunk (validated boundary)
#define SPF   16      // steps per prefetch window

// Scratch for x in case d_out only holds spikes (fallback; normally x goes to
// the second half of d_out).
__device__ float g_xbuf[8u * 2048u * 768u];

// ---------------------------------------------------------------------------
// Kernel 1 (R5-exact, validated — do not touch):
// x = LayerNorm(emb_w[token] + pos_w[s]) * gamma + beta
// One block per position s; warp w handles batch b=w (all warps share pos[s]).
// ---------------------------------------------------------------------------
__global__ void __launch_bounds__(256) emb_ln_kernel(
    const int* __restrict__ tok,
    const float* __restrict__ emb,
    const float* __restrict__ pos,
    const float* __restrict__ gamma,
    const float* __restrict__ beta,
    float* __restrict__ xout,
    int B, int S, int D)
{
    int s = blockIdx.x;
    int b = threadIdx.x >> 5;
    int lane = threadIdx.x & 31;
    if (b >= B) return;

    int row = b * S + s;
    int t = __ldg(tok + row);

    const int D4 = D >> 2;             // 192
    const int NV = D >> 7;             // 6

    const float4* e4 = reinterpret_cast<const float4*>(emb) + (size_t)t * D4;
    const float4* p4 = reinterpret_cast<const float4*>(pos) + (size_t)s * D4;

    float4 v[6];
    float sum = 0.f, ss = 0.f;
#pragma unroll 6
    for (int k = 0; k < NV; k++) {
        int idx = lane + (k << 5);
        float4 a = __ldcs(e4 + idx);        // streaming: no L2 reuse expected
        float4 p = __ldg(p4 + idx);
        float4 r;
        r.x = a.x + p.x; r.y = a.y + p.y; r.z = a.z + p.z; r.w = a.w + p.w;
        v[k] = r;
        sum += (r.x + r.y) + (r.z + r.w);
        ss = fmaf(r.x, r.x, ss);
        ss = fmaf(r.y, r.y, ss);
        ss = fmaf(r.z, r.z, ss);
        ss = fmaf(r.w, r.w, ss);
    }
#pragma unroll
    for (int o = 16; o > 0; o >>= 1) {
        sum += __shfl_xor_sync(0xffffffffu, sum, o);
        ss  += __shfl_xor_sync(0xffffffffu, ss,  o);
    }
    float inv_d = 1.0f / (float)D;
    float mu  = sum * inv_d;
    float var = fmaf(-mu, mu, ss * inv_d);
    float rstd = rsqrtf(var + LN_EPS);

    const float4* g4 = reinterpret_cast<const float4*>(gamma);
    const float4* b4 = reinterpret_cast<const float4*>(beta);
    float4* xo = reinterpret_cast<float4*>(xout) + (size_t)row * D4;

#pragma unroll 6
    for (int k = 0; k < NV; k++) {
        int idx = lane + (k << 5);
        float4 g = __ldg(g4 + idx);
        float4 bb = __ldg(b4 + idx);
        float4 r = v[k];
        float4 o;
        o.x = (r.x - mu) * rstd * g.x + bb.x;
        o.y = (r.y - mu) * rstd * g.y + bb.y;
        o.z = (r.z - mu) * rstd * g.z + bb.z;
        o.w = (r.w - mu) * rstd * g.w + bb.w;
        xo[idx] = o;                        // cache in L2 (re-read by scan)
    }
}

// ---------------------------------------------------------------------------
// Kernel 2: chunked LIF scan, 2 chains/thread (float2), FSET step,
// TRIPLE-buffered register prefetch (2-window lookahead covers L2 latency).
//   vr = v*LEAK + x_t ; s = (vr >= 1) as 1.0/0.0 (FSET) ; v = vr - s*vr
// Bit-identical to compare/select. CHUNK/WARM boundaries as validated.
// ---------------------------------------------------------------------------
__device__ __forceinline__ float fset_ge_thr(float a) {
    float r;
    asm("set.ge.f32.f32 %0, %1, %2;" : "=f"(r) : "f"(a), "f"(THRESH));
    return r;
}

__device__ __forceinline__ float lif_step(float& v, float xin) {
    float vr = fmaf(v, LEAK, xin);      // FFMA-imm (rt=1)
    float s = fset_ge_thr(vr);          // FSET -> {0.0f, 1.0f}
    v = fmaf(-s, vr, vr);               // exact reset
    return s;
}

template<int D2C>
__device__ __forceinline__ void load_win(float2 (&buf)[SPF],
                                         const float2* __restrict__ xp, int w)
{
    const float2* p = xp + (size_t)(w * SPF) * D2C;
#pragma unroll
    for (int i = 0; i < SPF; i++)
        buf[i] = __ldg(p + (size_t)i * D2C);
}

template<int D2C>
__device__ __forceinline__ void proc_win(float2 (&buf)[SPF],
                                         float2* __restrict__ sp,
                                         int w, int n_w,
                                         float& vx, float& vy)
{
    if (w * SPF >= n_w) {
        float2* o = sp + (size_t)(w * SPF - n_w) * D2C;
#pragma unroll
        for (int i = 0; i < SPF; i++) {
            float2 sv;
            sv.x = lif_step(vx, buf[i].x);
            sv.y = lif_step(vy, buf[i].y);
            __stcs(o + (size_t)i * D2C, sv);
        }
    } else {
#pragma unroll
        for (int i = 0; i < SPF; i++) {
            lif_step(vx, buf[i].x);
            lif_step(vy, buf[i].y);
        }
    }
}

template<int D2C>
__global__ void __launch_bounds__(128) lif_scan_tb(
    const float2* __restrict__ x,
    float2* __restrict__ spk,
    int S, int B)
{
    int q = blockIdx.x * blockDim.x + (int)threadIdx.x;   // chain-pair id
    int b = q / D2C;
    int d = q - b * D2C;
    if (b >= B) return;

    int t0 = blockIdx.y * CHUNK;
    int n_w = (t0 < WARM) ? t0 : WARM;    // 0,128,256 — multiples of SPF
    int tw = t0 - n_w;
    int total = n_w + CHUNK;              // 128,256,384
    int NW = total / SPF;                 // 8,16,24 windows

    const float2* xp = x   + ((size_t)b * S + tw) * D2C + d;
    float2*       sp = spk + ((size_t)b * S + t0) * D2C + d;

    float2 A[SPF], Bb[SPF], C[SPF];
    load_win<D2C>(A, xp, 0);
    load_win<D2C>(Bb, xp, 1);             // NW >= 8 always

    float vx = 0.f, vy = 0.f;

    for (int w = 0; w < NW; w += 3) {
        if (w + 2 < NW) load_win<D2C>(C, xp, w + 2);
        proc_win<D2C>(A, sp, w, n_w, vx, vy);

        if (w + 3 < NW) load_win<D2C>(A, xp, w + 3);
        if (w + 1 < NW) proc_win<D2C>(Bb, sp, w + 1, n_w, vx, vy);

        if (w + 4 < NW) load_win<D2C>(Bb, xp, w + 4);
        if (w + 2 < NW) proc_win<D2C>(C, sp, w + 2, n_w, vx, vy);
    }
}

// Generic fallback (runtime D2): validated double-buffer version.
__global__ void __launch_bounds__(128) lif_scan2_g(
    const float2* __restrict__ x,
    float2* __restrict__ spk,
    int S, int D2, int B)
{
    int q = blockIdx.x * blockDim.x + (int)threadIdx.x;
    int b = q / D2;
    int d = q - b * D2;
    if (b >= B) return;

    int t0 = blockIdx.y * CHUNK;
    int n_w = (t0 < WARM) ? t0 : WARM;
    int tw = t0 - n_w;
    int total = n_w + CHUNK;

    const float2* xp = x   + ((size_t)b * S + tw) * D2 + d;
    float2*       sp = spk + ((size_t)b * S + t0) * D2 + d;

    float2 A[SPF], Bb[SPF];
#pragma unroll
    for (int i = 0; i < SPF; i++)
        A[i] = __ldg(xp + (size_t)i * D2);

    float vx = 0.f, vy = 0.f;

    for (int s0 = 0; s0 < total; s0 += 2 * SPF) {
        {
            const float2* p = xp + (size_t)(s0 + SPF) * D2;
#pragma unroll
            for (int i = 0; i < SPF; i++)
                Bb[i] = __ldg(p + (size_t)i * D2);
        }
        if (s0 >= n_w) {
            float2* o = sp + (size_t)(s0 - n_w) * D2;
#pragma unroll
            for (int i = 0; i < SPF; i++) {
                float2 sv;
                sv.x = lif_step(vx, A[i].x);
                sv.y = lif_step(vy, A[i].y);
                __stcs(o + (size_t)i * D2, sv);
            }
        } else {
#pragma unroll
            for (int i = 0; i < SPF; i++) {
                lif_step(vx, A[i].x);
                lif_step(vy, A[i].y);
            }
        }
        if (s0 + 2 * SPF < total) {
            const float2* p = xp + (size_t)(s0 + 2 * SPF) * D2;
#pragma unroll
            for (int i = 0; i < SPF; i++)
                A[i] = __ldg(p + (size_t)i * D2);
        }
        int sB = s0 + SPF;
        if (sB >= n_w) {
            float2* o = sp + (size_t)(sB - n_w) * D2;
#pragma unroll
            for (int i = 0; i < SPF; i++) {
                float2 sv;
                sv.x = lif_step(vx, Bb[i].x);
                sv.y = lif_step(vy, Bb[i].y);
                __stcs(o + (size_t)i * D2, sv);
            }
        } else {
#pragma unroll
            for (int i = 0; i < SPF; i++) {
                lif_step(vx, Bb[i].x);
                lif_step(vy, Bb[i].y);
            }
        }
    }
}

// ---------------------------------------------------------------------------
// Launch. Inputs (metadata order): token_ids [B,S] i32, emb_w [V,D] f32,
// pos_w [S,D] f32, gamma [D] f32, beta [D] f32.
// Output: (spikes [B,S,D], x [B,S,D]) concatenated.
// ---------------------------------------------------------------------------
extern "C" void kernel_launch(void* const* d_in, const int* in_sizes, int n_in,
                              void* d_out, int out_size)
{
    const int*   tok   = (const int*)d_in[0];
    const float* emb   = (const float*)d_in[1];
    const float* pos   = (const float*)d_in[2];
    const float* gamma = (const float*)d_in[3];
    const float* beta  = (const float*)d_in[4];

    int BS = in_sizes[0];          // B*S
    int D  = in_sizes[3];          // 768
    int SD = in_sizes[2];          // S*D
    int S  = SD / D;
    int B  = BS / S;

    size_t BSD = (size_t)BS * (size_t)D;

    float* spikes = (float*)d_out;
    float* xout;
    if ((size_t)out_size >= 2 * BSD) {
        xout = spikes + BSD;       // x is second half of the tuple output
    } else {
        cudaGetSymbolAddress((void**)&xout, g_xbuf);
    }

    // Kernel 1: one block per position s, warp per batch b.
    emb_ln_kernel<<<S, 32 * B>>>(tok, emb, pos, gamma, beta, xout, B, S, D);

    // Kernel 2: 2 chains per thread, 128-thread blocks, chunks along y.
    int D2 = D >> 1;                         // 384
    int ngrp = B * D2;                       // 3072
    dim3 grid2((ngrp + 127) / 128, (S + CHUNK - 1) / CHUNK);
    if (D2 == 384) {
        lif_scan_tb<384><<<grid2, 128>>>((const float2*)xout, (float2*)spikes, S, B);
    } else {
        lif_scan2_g<<<grid2, 128>>>((const float2*)xout, (float2*)spikes, S, D2, B);
    }
}